// round 13
// baseline (speedup 1.0000x reference)
#include <cuda_runtime.h>

#define N_NODES 100000
#define N_EDGES 1200000
#define D_FEAT  64
#define D_OUT   128
#define SCAN_CHUNK  1024
#define SCAN_BLOCKS ((N_NODES + SCAN_CHUNK - 1) / SCAN_CHUNK)   // 98

// Scratch (no allocs allowed)
__device__ int g_esrc[N_EDGES];                 // src ids binned by dst
__device__ int g_rank[N_EDGES];                 // per-edge rank within its dst bin
__device__ int g_count[N_NODES];
__device__ int g_off[N_NODES + 1];
__device__ int g_bsum[SCAN_BLOCKS];
__device__ int g_bscan[SCAN_BLOCKS];
__device__ int g_arrive;
__device__ int g_release;

// ---------------------------------------------------------------------------
// K0: zero per-node counters + reset scan handshake flags (graph replays!).
// ---------------------------------------------------------------------------
__global__ void __launch_bounds__(256) init_kernel() {
    int i = blockIdx.x * 256 + threadIdx.x;
    if (i < N_NODES) g_count[i] = 0;
    if (i == 0) { g_arrive = 0; g_release = 0; }
}

// ---------------------------------------------------------------------------
// K1: count edges per dst; atomic return value = edge's rank in its bin.
// ---------------------------------------------------------------------------
__global__ void __launch_bounds__(256) count_kernel(const int* __restrict__ dst) {
    int e = blockIdx.x * 256 + threadIdx.x;
    if (e >= N_EDGES) return;
    int d = __ldg(dst + e);
    int r = ((unsigned)d < N_NODES) ? atomicAdd(&g_count[d], 1) : 0;
    g_rank[e] = r;                                   // coalesced
}

// ---------------------------------------------------------------------------
// K2: single-kernel two-level exclusive scan (arrival counter + release flag;
// arrival is non-blocking -> no residency deadlock; flags reset each replay).
// ---------------------------------------------------------------------------
__global__ void __launch_bounds__(256) scan_fused_kernel() {
    __shared__ int sh[256];
    __shared__ int sp[128];
    __shared__ int s_last;
    int b = blockIdx.x, tid = threadIdx.x;
    int base = b * SCAN_CHUNK + tid * 4;

    int c[4]; int s = 0;
    #pragma unroll
    for (int j = 0; j < 4; j++) {
        int i = base + j;
        c[j] = (i < N_NODES) ? g_count[i] : 0;
        s += c[j];
    }
    sh[tid] = s; __syncthreads();
    for (int o = 128; o; o >>= 1) { if (tid < o) sh[tid] += sh[tid + o]; __syncthreads(); }
    if (tid == 0) {
        g_bsum[b] = sh[0];
        __threadfence();
        s_last = (atomicAdd(&g_arrive, 1) == SCAN_BLOCKS - 1);
    }
    __syncthreads();

    if (s_last) {
        int v = (tid < SCAN_BLOCKS) ? g_bsum[tid] : 0;
        if (tid < 128) sp[tid] = v;
        __syncthreads();
        #pragma unroll
        for (int o = 1; o < 128; o <<= 1) {
            int t = (tid < 128 && tid >= o) ? sp[tid - o] : 0;
            __syncthreads();
            if (tid < 128) sp[tid] += t;
            __syncthreads();
        }
        if (tid < SCAN_BLOCKS) g_bscan[tid] = sp[tid] - v;   // exclusive
        if (tid == 127) g_off[N_NODES] = sp[127];            // total
        __threadfence();
        __syncthreads();
        if (tid == 0) atomicExch(&g_release, 1);
    }

    if (tid == 0) while (atomicAdd(&g_release, 0) == 0) {}
    __syncthreads();

    sh[tid] = s; __syncthreads();
    int v2 = s;
    #pragma unroll
    for (int o = 1; o < 256; o <<= 1) {
        int t = (tid >= o) ? sh[tid - o] : 0;
        __syncthreads();
        sh[tid] += t;
        __syncthreads();
    }
    int run = g_bscan[b] + (sh[tid] - v2);
    #pragma unroll
    for (int j = 0; j < 4; j++) {
        int i = base + j;
        if (i < N_NODES) { g_off[i] = run; run += c[j]; }
    }
}

// ---------------------------------------------------------------------------
// K3: bin edges by dst — NO atomics: slot = off[dst] + rank.
// ---------------------------------------------------------------------------
__global__ void __launch_bounds__(256) bin_kernel(
    const int* __restrict__ src, const int* __restrict__ dst)
{
    int e = blockIdx.x * 256 + threadIdx.x;
    if (e >= N_EDGES) return;
    int d = __ldg(dst + e);
    if ((unsigned)d >= N_NODES) return;
    g_esrc[__ldg(&g_off[d]) + __ldg(&g_rank[e])] = __ldg(src + e);
}

// ---------------------------------------------------------------------------
// K4: FUSED attention + FC — divergence-free half-split (R12 theory), with
// the R12 crash fixed: ALL __shfl_sync(FULL,...) are unconditional (indices
// clamped); only loads/accumulation are predicated.  Full warp per node;
// per iteration the warp covers 4 edges (half h takes edges 4j+2h, 4j+2h+1).
// Identical trip counts in both halves -> no intra-warp serialization.
// ---------------------------------------------------------------------------
__device__ __forceinline__ void accum4(float4& acc, const float4 r,
                                       const float4 w0, const float4 w1,
                                       const float4 w2, const float4 w3) {
    acc.x = fmaf(r.x, w0.x, fmaf(r.y, w1.x, fmaf(r.z, w2.x, fmaf(r.w, w3.x, acc.x))));
    acc.y = fmaf(r.x, w0.y, fmaf(r.y, w1.y, fmaf(r.z, w2.y, fmaf(r.w, w3.y, acc.y))));
    acc.z = fmaf(r.x, w0.z, fmaf(r.y, w1.z, fmaf(r.z, w2.z, fmaf(r.w, w3.z, acc.z))));
    acc.w = fmaf(r.x, w0.w, fmaf(r.y, w1.w, fmaf(r.z, w2.w, fmaf(r.w, w3.w, acc.w))));
}

__device__ __forceinline__ float4 relu4(float4 v) {
    v.x = fmaxf(v.x, 0.f); v.y = fmaxf(v.y, 0.f);
    v.z = fmaxf(v.z, 0.f); v.w = fmaxf(v.w, 0.f);
    return v;
}

__device__ __forceinline__ float dot4(const float4 a, const float4 u) {
    return fmaf(a.x, u.x, fmaf(a.y, u.y, fmaf(a.z, u.z, a.w * u.w)));
}

__global__ void __launch_bounds__(256) attn_fc_kernel(
    const float* __restrict__ hk, const float* __restrict__ hu,
    const float* __restrict__ W, const float* __restrict__ b,
    float* __restrict__ out)
{
    // [0,8192): Wt[k*128+j];  [8192,12288): staging 8 warps x 8 nodes x 64
    __shared__ float sh[12288];                          // 48 KB
    float* Wt = sh;
    int tid = threadIdx.x;
    for (int i = tid; i < D_FEAT * D_OUT; i += 256) {
        int k = i >> 7;            // input feat
        int j = i & 127;           // output feat
        Wt[i] = __ldg(W + j * D_FEAT + k);               // coalesced STS
    }
    __syncthreads();

    const unsigned FULL = 0xffffffffu;
    int wid = tid >> 5, lane = tid & 31;
    int half = lane >> 4, hl = lane & 15;
    float* stage = sh + 8192 + wid * 512;                // 8 nodes x 64 feats
    float4* stage4 = (float4*)stage;
    const float4* hk4 = (const float4*)hk;
    const float4* Wt4 = (const float4*)Wt;
    float4* out4 = (float4*)out;

    int nbase = (blockIdx.x * 8 + wid) * 8;              // 8 nodes per warp

    // ---- attention: whole warp on each node; halves split the edge list ----
    for (int m = 0; m < 8; m++) {
        int node = nbase + m;
        if (node >= N_NODES) break;                      // warp-uniform
        float4 u = __ldg((const float4*)hu + (size_t)node * 16 + hl);
        int beg = __ldg(&g_off[node]), end = __ldg(&g_off[node + 1]);
        float4 acc = make_float4(0.f, 0.f, 0.f, 0.f);
        float denom = 0.f;

        for (int base = beg; base < end; base += 32) {   // warp-uniform trip count
            int n = min(32, end - base);
            int srcid = (lane < n) ? __ldg(&g_esrc[base + lane]) : 0;

            // prime: shuffles unconditional, loads predicated
            float4 a0 = make_float4(0.f, 0.f, 0.f, 0.f);
            float4 a1 = a0;
            {
                int k0 = 2 * half, k1 = k0 + 1;
                int s0 = __shfl_sync(FULL, srcid, k0);   // all lanes participate
                int s1 = __shfl_sync(FULL, srcid, k1);
                if (k0 < n) a0 = __ldg(hk4 + (size_t)s0 * 16 + hl);
                if (k1 < n) a1 = __ldg(hk4 + (size_t)s1 * 16 + hl);
            }
            int iters = (n + 3) >> 2;                    // identical in both halves
            for (int j = 0; j < iters; j++) {
                int k0 = 4 * j + 2 * half, k1 = k0 + 1;
                float4 c0 = a0, c1 = a1;
                // prefetch: shfl UNCONDITIONAL (clamped idx), load predicated.
                // (R12 bug: these shfls sat inside half-divergent branches ->
                //  FULL-mask shfl with missing lanes -> illegal instruction.)
                int p0 = min(k0 + 4, 31), p1 = min(k1 + 4, 31);
                int t0 = __shfl_sync(FULL, srcid, p0);
                int t1 = __shfl_sync(FULL, srcid, p1);
                if (k0 + 4 < n) a0 = __ldg(hk4 + (size_t)t0 * 16 + hl);
                if (k1 + 4 < n) a1 = __ldg(hk4 + (size_t)t1 * 16 + hl);

                float q0 = dot4(c0, u);
                float q1 = dot4(c1, u);
                #pragma unroll
                for (int o = 8; o; o >>= 1) {            // unconditional reduces
                    q0 += __shfl_xor_sync(FULL, q0, o, 16);
                    q1 += __shfl_xor_sync(FULL, q1, o, 16);
                }
                if (k0 < n) {                            // no sync ops inside
                    float e0 = __expf(q0);
                    acc.x = fmaf(e0, c0.x, acc.x);
                    acc.y = fmaf(e0, c0.y, acc.y);
                    acc.z = fmaf(e0, c0.z, acc.z);
                    acc.w = fmaf(e0, c0.w, acc.w);
                    denom += e0;
                }
                if (k1 < n) {
                    float e1 = __expf(q1);
                    acc.x = fmaf(e1, c1.x, acc.x);
                    acc.y = fmaf(e1, c1.y, acc.y);
                    acc.z = fmaf(e1, c1.z, acc.z);
                    acc.w = fmaf(e1, c1.w, acc.w);
                    denom += e1;
                }
            }
        }
        // combine halves (feats align: lane hl <-> lane hl+16); unconditional
        acc.x += __shfl_xor_sync(FULL, acc.x, 16);
        acc.y += __shfl_xor_sync(FULL, acc.y, 16);
        acc.z += __shfl_xor_sync(FULL, acc.z, 16);
        acc.w += __shfl_xor_sync(FULL, acc.w, 16);
        denom += __shfl_xor_sync(FULL, denom, 16);
        float inv = (end > beg) ? 1.f / denom : 0.f;     // deg==0 -> zero row
        if (half == 0)
            stage4[m * 16 + hl] =
                make_float4(acc.x * inv, acc.y * inv, acc.z * inv, acc.w * inv);
    }
    __syncwarp();   // staging visible before FC

    // ---- FC + relu: two 4-node groups (R9's best-measured shape) ----
    float4 bb = __ldg((const float4*)b + lane);
    #pragma unroll
    for (int g = 0; g < 2; g++) {
        int gbase = nbase + g * 4;
        if (gbase >= N_NODES) break;
        float4 a0 = bb, a1 = bb, a2 = bb, a3 = bb;
        #pragma unroll 4
        for (int kc4 = 0; kc4 < 16; kc4++) {
            float4 w0 = Wt4[(kc4 * 4 + 0) * 32 + lane];
            float4 w1 = Wt4[(kc4 * 4 + 1) * 32 + lane];
            float4 w2 = Wt4[(kc4 * 4 + 2) * 32 + lane];
            float4 w3 = Wt4[(kc4 * 4 + 3) * 32 + lane];
            float4 r0 = stage4[(g * 4 + 0) * 16 + kc4];
            float4 r1 = stage4[(g * 4 + 1) * 16 + kc4];
            float4 r2 = stage4[(g * 4 + 2) * 16 + kc4];
            float4 r3 = stage4[(g * 4 + 3) * 16 + kc4];
            accum4(a0, r0, w0, w1, w2, w3);
            accum4(a1, r1, w0, w1, w2, w3);
            accum4(a2, r2, w0, w1, w2, w3);
            accum4(a3, r3, w0, w1, w2, w3);
        }
        if (gbase + 0 < N_NODES) out4[(size_t)(gbase + 0) * 32 + lane] = relu4(a0);
        if (gbase + 1 < N_NODES) out4[(size_t)(gbase + 1) * 32 + lane] = relu4(a1);
        if (gbase + 2 < N_NODES) out4[(size_t)(gbase + 2) * 32 + lane] = relu4(a2);
        if (gbase + 3 < N_NODES) out4[(size_t)(gbase + 3) * 32 + lane] = relu4(a3);
    }
}

// ---------------------------------------------------------------------------
// Inputs: hk[f32 N*64], hu[f32 N*64], W[f32 128*64], b[f32 128],
//         src[i32 E], dst[i32 E].  Output: f32 N*128.
// ---------------------------------------------------------------------------
extern "C" void kernel_launch(void* const* d_in, const int* in_sizes, int n_in,
                              void* d_out, int out_size) {
    const float* hk  = (const float*)d_in[0];
    const float* hu  = (const float*)d_in[1];
    const float* W   = (const float*)d_in[2];
    const float* b   = (const float*)d_in[3];
    const int*   src = (const int*)d_in[4];
    const int*   dst = (const int*)d_in[5];
    float* out = (float*)d_out;

    init_kernel<<<(N_NODES + 255) / 256, 256>>>();
    count_kernel<<<(N_EDGES + 255) / 256, 256>>>(dst);
    scan_fused_kernel<<<SCAN_BLOCKS, 256>>>();
    bin_kernel<<<(N_EDGES + 255) / 256, 256>>>(src, dst);
    attn_fc_kernel<<<(N_NODES + 63) / 64, 256>>>(hk, hu, W, b, out);
}

// round 14
// speedup vs baseline: 1.4664x; 1.4664x over previous
#include <cuda_runtime.h>

#define N_NODES 100000
#define N_EDGES 1200000
#define D_FEAT  64
#define D_OUT   128
#define SCAN_CHUNK  1024
#define SCAN_BLOCKS ((N_NODES + SCAN_CHUNK - 1) / SCAN_CHUNK)   // 98
#define W_STRIDE 136      // padded [64][136] -> conflict-free B-frag LDS
#define S_STRIDE 68       // padded staging row stride -> conflict-free A-frag LDS
#define SMEM_FLOATS (64 * W_STRIDE + 8 * 16 * S_STRIDE)   // 8704 + 8704
#define SMEM_BYTES (SMEM_FLOATS * 4)                       // 69632

// Scratch (no allocs allowed)
__device__ int g_esrc[N_EDGES];
__device__ int g_rank[N_EDGES];
__device__ int g_count[N_NODES];
__device__ int g_off[N_NODES + 1];
__device__ int g_bsum[SCAN_BLOCKS];
__device__ int g_bscan[SCAN_BLOCKS];
__device__ int g_arrive;
__device__ int g_release;
__device__ float g_Wt[64 * W_STRIDE];   // W transposed [k][n], padded, tf32-rounded

// ---------------------------------------------------------------------------
// K0: zero counters, reset scan flags, build tf32 Wt (deterministic per call).
// ---------------------------------------------------------------------------
__global__ void __launch_bounds__(256) init_kernel(const float* __restrict__ W) {
    int i = blockIdx.x * 256 + threadIdx.x;
    if (i < N_NODES) g_count[i] = 0;
    if (i == 0) { g_arrive = 0; g_release = 0; }
    if (i < 64 * W_STRIDE) {
        int k = i / W_STRIDE, n = i % W_STRIDE;
        float v = (n < D_OUT) ? __ldg(&W[n * D_FEAT + k]) : 0.f;
        unsigned t;
        asm("cvt.rna.tf32.f32 %0, %1;" : "=r"(t) : "f"(v));   // pre-round once
        g_Wt[i] = __uint_as_float(t);
    }
}

// ---------------------------------------------------------------------------
// K1: count edges per dst; atomic return value = edge's rank in its bin.
// ---------------------------------------------------------------------------
__global__ void __launch_bounds__(256) count_kernel(const int* __restrict__ dst) {
    int e = blockIdx.x * 256 + threadIdx.x;
    if (e >= N_EDGES) return;
    int d = __ldg(dst + e);
    int r = ((unsigned)d < N_NODES) ? atomicAdd(&g_count[d], 1) : 0;
    g_rank[e] = r;
}

// ---------------------------------------------------------------------------
// K2: single-kernel two-level exclusive scan (non-blocking arrival + release).
// ---------------------------------------------------------------------------
__global__ void __launch_bounds__(256) scan_fused_kernel() {
    __shared__ int sh[256];
    __shared__ int sp[128];
    __shared__ int s_last;
    int b = blockIdx.x, tid = threadIdx.x;
    int base = b * SCAN_CHUNK + tid * 4;

    int c[4]; int s = 0;
    #pragma unroll
    for (int j = 0; j < 4; j++) {
        int i = base + j;
        c[j] = (i < N_NODES) ? g_count[i] : 0;
        s += c[j];
    }
    sh[tid] = s; __syncthreads();
    for (int o = 128; o; o >>= 1) { if (tid < o) sh[tid] += sh[tid + o]; __syncthreads(); }
    if (tid == 0) {
        g_bsum[b] = sh[0];
        __threadfence();
        s_last = (atomicAdd(&g_arrive, 1) == SCAN_BLOCKS - 1);
    }
    __syncthreads();

    if (s_last) {
        int v = (tid < SCAN_BLOCKS) ? g_bsum[tid] : 0;
        if (tid < 128) sp[tid] = v;
        __syncthreads();
        #pragma unroll
        for (int o = 1; o < 128; o <<= 1) {
            int t = (tid < 128 && tid >= o) ? sp[tid - o] : 0;
            __syncthreads();
            if (tid < 128) sp[tid] += t;
            __syncthreads();
        }
        if (tid < SCAN_BLOCKS) g_bscan[tid] = sp[tid] - v;
        if (tid == 127) g_off[N_NODES] = sp[127];
        __threadfence();
        __syncthreads();
        if (tid == 0) atomicExch(&g_release, 1);
    }

    if (tid == 0) while (atomicAdd(&g_release, 0) == 0) {}
    __syncthreads();

    sh[tid] = s; __syncthreads();
    int v2 = s;
    #pragma unroll
    for (int o = 1; o < 256; o <<= 1) {
        int t = (tid >= o) ? sh[tid - o] : 0;
        __syncthreads();
        sh[tid] += t;
        __syncthreads();
    }
    int run = g_bscan[b] + (sh[tid] - v2);
    #pragma unroll
    for (int j = 0; j < 4; j++) {
        int i = base + j;
        if (i < N_NODES) { g_off[i] = run; run += c[j]; }
    }
}

// ---------------------------------------------------------------------------
// K3: bin edges by dst — atomic-free: slot = off[dst] + rank.
// ---------------------------------------------------------------------------
__global__ void __launch_bounds__(256) bin_kernel(
    const int* __restrict__ src, const int* __restrict__ dst)
{
    int e = blockIdx.x * 256 + threadIdx.x;
    if (e >= N_EDGES) return;
    int d = __ldg(dst + e);
    if ((unsigned)d >= N_NODES) return;
    g_esrc[__ldg(&g_off[d]) + __ldg(&g_rank[e])] = __ldg(src + e);
}

// ---------------------------------------------------------------------------
// K4: attention (R9-exact half-split, best measured) + TENSOR-CORE FC.
// Warp owns 16 nodes (8 per 16-lane half). Attention stages rst rows into
// padded smem; FC = mma.sync.m16n8k8 tf32 (16 nodes x 128 outs per warp):
// replaces 25.6M FFMA (48us floor) with 800K HMMA (~5us).  W pre-rounded to
// tf32 in init; bias folded into accumulator init; ReLU in regs.
// ---------------------------------------------------------------------------
__device__ __forceinline__ float dot4(const float4 a, const float4 u) {
    return fmaf(a.x, u.x, fmaf(a.y, u.y, fmaf(a.z, u.z, a.w * u.w)));
}

__device__ __forceinline__ unsigned to_tf32(float x) {
    unsigned t;
    asm("cvt.rna.tf32.f32 %0, %1;" : "=r"(t) : "f"(x));
    return t;
}

extern __shared__ float sh[];   // [0,8704): Wt_s  [8704,17408): staging

__global__ void __launch_bounds__(256) attn_fc_kernel(
    const float* __restrict__ hk, const float* __restrict__ hu,
    const float* __restrict__ b, float* __restrict__ out)
{
    float* Wt_s = sh;
    int tid = threadIdx.x;
    for (int i = tid; i < 64 * W_STRIDE; i += 256)       // coalesced
        Wt_s[i] = g_Wt[i];
    __syncthreads();

    int wid = tid >> 5, lane = tid & 31;
    int half = lane >> 4, hl = lane & 15;
    unsigned hm = half ? 0xFFFF0000u : 0x0000FFFFu;
    float* stage = sh + 64 * W_STRIDE + wid * 16 * S_STRIDE;   // 16 rows x 68
    const float4* hk4 = (const float4*)hk;

    int nbase = (blockIdx.x * 8 + wid) * 16;             // 16 nodes per warp
    int hbase = nbase + half * 8;                        // 8 per half-warp

    // ---- attention (R9 inner loop, unchanged) ----
    for (int m = 0; m < 8; m++) {
        int node = hbase + m;
        if (node >= N_NODES) break;                      // half-uniform
        float4 u = __ldg((const float4*)hu + (size_t)node * 16 + hl);
        int beg = __ldg(&g_off[node]), end = __ldg(&g_off[node + 1]);
        float4 acc = make_float4(0.f, 0.f, 0.f, 0.f);
        float denom = 0.f;

        for (int base = beg; base < end; base += 16) {
            int n = min(16, end - base);
            int srcid = (hl < n) ? __ldg(&g_esrc[base + hl]) : 0;

            float4 a0, a1;                               // pipeline prime
            {
                int s0 = __shfl_sync(hm, srcid, 0, 16);
                a0 = __ldg(hk4 + (size_t)s0 * 16 + hl);
                if (n >= 2) {
                    int s1 = __shfl_sync(hm, srcid, 1, 16);
                    a1 = __ldg(hk4 + (size_t)s1 * 16 + hl);
                }
            }
            int j = 0;
            for (; j + 2 <= n; j += 2) {
                float4 c0 = a0, c1 = a1;
                if (j + 4 <= n) {                        // prefetch next pair
                    int t0 = __shfl_sync(hm, srcid, j + 2, 16);
                    int t1 = __shfl_sync(hm, srcid, j + 3, 16);
                    a0 = __ldg(hk4 + (size_t)t0 * 16 + hl);
                    a1 = __ldg(hk4 + (size_t)t1 * 16 + hl);
                } else if (j + 3 == n) {
                    int t0 = __shfl_sync(hm, srcid, j + 2, 16);
                    a0 = __ldg(hk4 + (size_t)t0 * 16 + hl);
                }
                float p0 = dot4(c0, u);
                float p1 = dot4(c1, u);
                #pragma unroll
                for (int o = 8; o; o >>= 1) {
                    p0 += __shfl_xor_sync(hm, p0, o, 16);
                    p1 += __shfl_xor_sync(hm, p1, o, 16);
                }
                float e0 = __expf(p0);
                float e1 = __expf(p1);
                acc.x = fmaf(e0, c0.x, fmaf(e1, c1.x, acc.x));
                acc.y = fmaf(e0, c0.y, fmaf(e1, c1.y, acc.y));
                acc.z = fmaf(e0, c0.z, fmaf(e1, c1.z, acc.z));
                acc.w = fmaf(e0, c0.w, fmaf(e1, c1.w, acc.w));
                denom += e0 + e1;
            }
            if (j < n) {
                float p0 = dot4(a0, u);
                #pragma unroll
                for (int o = 8; o; o >>= 1) p0 += __shfl_xor_sync(hm, p0, o, 16);
                float e0 = __expf(p0);
                acc.x = fmaf(e0, a0.x, acc.x);
                acc.y = fmaf(e0, a0.y, acc.y);
                acc.z = fmaf(e0, a0.z, acc.z);
                acc.w = fmaf(e0, a0.w, acc.w);
                denom += e0;
            }
        }
        float inv = (end > beg) ? 1.f / denom : 0.f;     // deg==0 -> zero row
        int row = half * 8 + m;
        float* sp = stage + row * S_STRIDE + hl * 4;     // padded, conflict-free
        sp[0] = acc.x * inv; sp[1] = acc.y * inv;
        sp[2] = acc.z * inv; sp[3] = acc.w * inv;
    }
    __syncwarp();

    // ---- FC via mma.sync m16n8k8 tf32: D(16x8) = A(16x8k) B(8kx8) + bias ----
    int g = lane >> 2, t = lane & 3;
    // A fragments: 8 k-steps x 4 regs, loaded once (conflict-free via pad 68)
    unsigned A0[8], A1[8], A2[8], A3[8];
    #pragma unroll
    for (int ks = 0; ks < 8; ks++) {
        A0[ks] = to_tf32(stage[ g      * S_STRIDE + ks * 8 + t    ]);
        A1[ks] = to_tf32(stage[(g + 8) * S_STRIDE + ks * 8 + t    ]);
        A2[ks] = to_tf32(stage[ g      * S_STRIDE + ks * 8 + t + 4]);
        A3[ks] = to_tf32(stage[(g + 8) * S_STRIDE + ks * 8 + t + 4]);
    }
    int n0 = nbase + g, n1 = n0 + 8;
    float2* out2 = (float2*)out;

    #pragma unroll 4
    for (int nt = 0; nt < 16; nt++) {
        float2 bb = __ldg((const float2*)b + nt * 4 + t);   // cols nt*8+2t,+1
        float c0 = bb.x, c1 = bb.y, c2 = bb.x, c3 = bb.y;
        #pragma unroll
        for (int ks = 0; ks < 8; ks++) {
            unsigned b0 = __float_as_uint(Wt_s[(ks * 8 + t    ) * W_STRIDE + nt * 8 + g]);
            unsigned b1 = __float_as_uint(Wt_s[(ks * 8 + t + 4) * W_STRIDE + nt * 8 + g]);
            asm volatile(
                "mma.sync.aligned.m16n8k8.row.col.f32.tf32.tf32.f32 "
                "{%0,%1,%2,%3}, {%4,%5,%6,%7}, {%8,%9}, {%0,%1,%2,%3};"
                : "+f"(c0), "+f"(c1), "+f"(c2), "+f"(c3)
                : "r"(A0[ks]), "r"(A1[ks]), "r"(A2[ks]), "r"(A3[ks]),
                  "r"(b0), "r"(b1));
        }
        c0 = fmaxf(c0, 0.f); c1 = fmaxf(c1, 0.f);
        c2 = fmaxf(c2, 0.f); c3 = fmaxf(c3, 0.f);
        if (n0 < N_NODES) out2[(size_t)n0 * 64 + nt * 4 + t] = make_float2(c0, c1);
        if (n1 < N_NODES) out2[(size_t)n1 * 64 + nt * 4 + t] = make_float2(c2, c3);
    }
}

// ---------------------------------------------------------------------------
// Inputs: hk[f32 N*64], hu[f32 N*64], W[f32 128*64], b[f32 128],
//         src[i32 E], dst[i32 E].  Output: f32 N*128.
// ---------------------------------------------------------------------------
extern "C" void kernel_launch(void* const* d_in, const int* in_sizes, int n_in,
                              void* d_out, int out_size) {
    const float* hk  = (const float*)d_in[0];
    const float* hu  = (const float*)d_in[1];
    const float* W   = (const float*)d_in[2];
    const float* b   = (const float*)d_in[3];
    const int*   src = (const int*)d_in[4];
    const int*   dst = (const int*)d_in[5];
    float* out = (float*)d_out;

    cudaFuncSetAttribute(attn_fc_kernel,
                         cudaFuncAttributeMaxDynamicSharedMemorySize, SMEM_BYTES);

    init_kernel<<<(N_NODES + 255) / 256, 256>>>(W);
    count_kernel<<<(N_EDGES + 255) / 256, 256>>>(dst);
    scan_fused_kernel<<<SCAN_BLOCKS, 256>>>();
    bin_kernel<<<(N_EDGES + 255) / 256, 256>>>(src, dst);
    // 8 warps/block x 16 nodes/warp = 128 nodes/block
    attn_fc_kernel<<<(N_NODES + 127) / 128, 256, SMEM_BYTES>>>(hk, hu, b, out);
}

// round 15
// speedup vs baseline: 1.4872x; 1.0142x over previous
#include <cuda_runtime.h>

#define N_NODES 100000
#define N_EDGES 1200000
#define D_FEAT  64
#define D_OUT   128
#define SCAN_CHUNK  1024
#define SCAN_BLOCKS ((N_NODES + SCAN_CHUNK - 1) / SCAN_CHUNK)   // 98
#define W_STRIDE 136      // padded [64][136] -> conflict-free B-frag LDS
#define S_STRIDE 68       // padded staging row stride -> conflict-free A-frag LDS
#define SMEM_FLOATS (64 * W_STRIDE + 8 * 16 * S_STRIDE)   // 8704 + 8704
#define SMEM_BYTES (SMEM_FLOATS * 4)                       // 69632

// Scratch (no allocs allowed)
__device__ int g_esrc[N_EDGES];
__device__ int g_rank[N_EDGES];
__device__ int g_count[N_NODES];
__device__ int g_off[N_NODES + 1];
__device__ int g_bsum[SCAN_BLOCKS];
__device__ int g_bscan[SCAN_BLOCKS];
__device__ int g_arrive;
__device__ int g_release;
__device__ float g_Wt[64 * W_STRIDE];   // W transposed [k][n], padded, tf32-rounded

// ---------------------------------------------------------------------------
// K0: zero counters, reset scan flags, build tf32 Wt (deterministic per call).
// ---------------------------------------------------------------------------
__global__ void __launch_bounds__(256) init_kernel(const float* __restrict__ W) {
    int i = blockIdx.x * 256 + threadIdx.x;
    if (i < N_NODES) g_count[i] = 0;
    if (i == 0) { g_arrive = 0; g_release = 0; }
    if (i < 64 * W_STRIDE) {
        int k = i / W_STRIDE, n = i % W_STRIDE;
        float v = (n < D_OUT) ? __ldg(&W[n * D_FEAT + k]) : 0.f;
        unsigned t;
        asm("cvt.rna.tf32.f32 %0, %1;" : "=r"(t) : "f"(v));
        g_Wt[i] = __uint_as_float(t);
    }
}

// ---------------------------------------------------------------------------
// K1: count+rank, 4 edges/thread (int4 loads/stores, MLP=4).
// ---------------------------------------------------------------------------
__global__ void __launch_bounds__(256) count_kernel(const int* __restrict__ dst) {
    int q = blockIdx.x * 256 + threadIdx.x;            // quad index
    if (q * 4 >= N_EDGES) return;
    int4 d4 = __ldg((const int4*)dst + q);             // N_EDGES % 4 == 0
    int4 r4;
    r4.x = ((unsigned)d4.x < N_NODES) ? atomicAdd(&g_count[d4.x], 1) : 0;
    r4.y = ((unsigned)d4.y < N_NODES) ? atomicAdd(&g_count[d4.y], 1) : 0;
    r4.z = ((unsigned)d4.z < N_NODES) ? atomicAdd(&g_count[d4.z], 1) : 0;
    r4.w = ((unsigned)d4.w < N_NODES) ? atomicAdd(&g_count[d4.w], 1) : 0;
    ((int4*)g_rank)[q] = r4;
}

// ---------------------------------------------------------------------------
// K2: single-kernel two-level exclusive scan (non-blocking arrival + release).
// ---------------------------------------------------------------------------
__global__ void __launch_bounds__(256) scan_fused_kernel() {
    __shared__ int sh[256];
    __shared__ int sp[128];
    __shared__ int s_last;
    int b = blockIdx.x, tid = threadIdx.x;
    int base = b * SCAN_CHUNK + tid * 4;

    int c[4]; int s = 0;
    #pragma unroll
    for (int j = 0; j < 4; j++) {
        int i = base + j;
        c[j] = (i < N_NODES) ? g_count[i] : 0;
        s += c[j];
    }
    sh[tid] = s; __syncthreads();
    for (int o = 128; o; o >>= 1) { if (tid < o) sh[tid] += sh[tid + o]; __syncthreads(); }
    if (tid == 0) {
        g_bsum[b] = sh[0];
        __threadfence();
        s_last = (atomicAdd(&g_arrive, 1) == SCAN_BLOCKS - 1);
    }
    __syncthreads();

    if (s_last) {
        int v = (tid < SCAN_BLOCKS) ? g_bsum[tid] : 0;
        if (tid < 128) sp[tid] = v;
        __syncthreads();
        #pragma unroll
        for (int o = 1; o < 128; o <<= 1) {
            int t = (tid < 128 && tid >= o) ? sp[tid - o] : 0;
            __syncthreads();
            if (tid < 128) sp[tid] += t;
            __syncthreads();
        }
        if (tid < SCAN_BLOCKS) g_bscan[tid] = sp[tid] - v;
        if (tid == 127) g_off[N_NODES] = sp[127];
        __threadfence();
        __syncthreads();
        if (tid == 0) atomicExch(&g_release, 1);
    }

    if (tid == 0) while (atomicAdd(&g_release, 0) == 0) {}
    __syncthreads();

    sh[tid] = s; __syncthreads();
    int v2 = s;
    #pragma unroll
    for (int o = 1; o < 256; o <<= 1) {
        int t = (tid >= o) ? sh[tid - o] : 0;
        __syncthreads();
        sh[tid] += t;
        __syncthreads();
    }
    int run = g_bscan[b] + (sh[tid] - v2);
    #pragma unroll
    for (int j = 0; j < 4; j++) {
        int i = base + j;
        if (i < N_NODES) { g_off[i] = run; run += c[j]; }
    }
}

// ---------------------------------------------------------------------------
// K3: bin, 4 edges/thread — atomic-free scatter with MLP=4.
// ---------------------------------------------------------------------------
__global__ void __launch_bounds__(256) bin_kernel(
    const int* __restrict__ src, const int* __restrict__ dst)
{
    int q = blockIdx.x * 256 + threadIdx.x;
    if (q * 4 >= N_EDGES) return;
    int4 d4 = __ldg((const int4*)dst + q);
    int4 r4 = __ldg((const int4*)g_rank + q);
    int4 s4 = __ldg((const int4*)src + q);
    if ((unsigned)d4.x < N_NODES) g_esrc[__ldg(&g_off[d4.x]) + r4.x] = s4.x;
    if ((unsigned)d4.y < N_NODES) g_esrc[__ldg(&g_off[d4.y]) + r4.y] = s4.y;
    if ((unsigned)d4.z < N_NODES) g_esrc[__ldg(&g_off[d4.z]) + r4.z] = s4.z;
    if ((unsigned)d4.w < N_NODES) g_esrc[__ldg(&g_off[d4.w]) + r4.w] = s4.w;
}

// ---------------------------------------------------------------------------
// K4: attention (half-split, now 4 chains in flight) + tensor-core FC.
// Per quad of edges: 4 broadcasts -> 4 LDG.128 issued together -> 4
// interleaved shuffle-reduces -> gated exp/accum.  All shuffles
// unconditional; predicates are half-uniform (k+i<n same across the half).
// ---------------------------------------------------------------------------
__device__ __forceinline__ float dot4(const float4 a, const float4 u) {
    return fmaf(a.x, u.x, fmaf(a.y, u.y, fmaf(a.z, u.z, a.w * u.w)));
}

__device__ __forceinline__ unsigned to_tf32(float x) {
    unsigned t;
    asm("cvt.rna.tf32.f32 %0, %1;" : "=r"(t) : "f"(x));
    return t;
}

extern __shared__ float sh[];   // [0,8704): Wt_s  [8704,17408): staging

__global__ void __launch_bounds__(256) attn_fc_kernel(
    const float* __restrict__ hk, const float* __restrict__ hu,
    const float* __restrict__ b, float* __restrict__ out)
{
    float* Wt_s = sh;
    int tid = threadIdx.x;
    for (int i = tid; i < 64 * W_STRIDE; i += 256)
        Wt_s[i] = g_Wt[i];
    __syncthreads();

    int wid = tid >> 5, lane = tid & 31;
    int half = lane >> 4, hl = lane & 15;
    unsigned hm = half ? 0xFFFF0000u : 0x0000FFFFu;
    float* stage = sh + 64 * W_STRIDE + wid * 16 * S_STRIDE;   // 16 rows x 68
    const float4* hk4 = (const float4*)hk;

    int nbase = (blockIdx.x * 8 + wid) * 16;             // 16 nodes per warp
    int hbase = nbase + half * 8;                        // 8 per half-warp

    // ---- attention: 8 nodes per half; 4 edge-chains in flight ----
    for (int m = 0; m < 8; m++) {
        int node = hbase + m;
        if (node >= N_NODES) break;                      // half-uniform
        float4 u = __ldg((const float4*)hu + (size_t)node * 16 + hl);
        int beg = __ldg(&g_off[node]), end = __ldg(&g_off[node + 1]);
        float4 acc = make_float4(0.f, 0.f, 0.f, 0.f);
        float denom = 0.f;

        for (int base = beg; base < end; base += 16) {
            int n = min(16, end - base);                 // half-uniform
            int srcid = (hl < n) ? __ldg(&g_esrc[base + hl]) : 0;

            for (int k0 = 0; k0 < n; k0 += 4) {          // half-uniform trips
                // 4 broadcasts (unconditional, clamped), then 4 loads together
                int s0 = __shfl_sync(hm, srcid, min(k0 + 0, 15), 16);
                int s1 = __shfl_sync(hm, srcid, min(k0 + 1, 15), 16);
                int s2 = __shfl_sync(hm, srcid, min(k0 + 2, 15), 16);
                int s3 = __shfl_sync(hm, srcid, min(k0 + 3, 15), 16);
                float4 a0 = make_float4(0.f, 0.f, 0.f, 0.f);
                float4 a1 = a0, a2 = a0, a3 = a0;
                a0 = __ldg(hk4 + (size_t)s0 * 16 + hl);          // k0 < n always
                if (k0 + 1 < n) a1 = __ldg(hk4 + (size_t)s1 * 16 + hl);
                if (k0 + 2 < n) a2 = __ldg(hk4 + (size_t)s2 * 16 + hl);
                if (k0 + 3 < n) a3 = __ldg(hk4 + (size_t)s3 * 16 + hl);

                float p0 = dot4(a0, u), p1 = dot4(a1, u);
                float p2 = dot4(a2, u), p3 = dot4(a3, u);
                #pragma unroll
                for (int o = 8; o; o >>= 1) {            // 4 interleaved reduces
                    p0 += __shfl_xor_sync(hm, p0, o, 16);
                    p1 += __shfl_xor_sync(hm, p1, o, 16);
                    p2 += __shfl_xor_sync(hm, p2, o, 16);
                    p3 += __shfl_xor_sync(hm, p3, o, 16);
                }
                {
                    float e0 = __expf(p0);               // edge k0 always valid
                    acc.x = fmaf(e0, a0.x, acc.x); acc.y = fmaf(e0, a0.y, acc.y);
                    acc.z = fmaf(e0, a0.z, acc.z); acc.w = fmaf(e0, a0.w, acc.w);
                    denom += e0;
                }
                if (k0 + 1 < n) {
                    float e1 = __expf(p1);
                    acc.x = fmaf(e1, a1.x, acc.x); acc.y = fmaf(e1, a1.y, acc.y);
                    acc.z = fmaf(e1, a1.z, acc.z); acc.w = fmaf(e1, a1.w, acc.w);
                    denom += e1;
                }
                if (k0 + 2 < n) {
                    float e2 = __expf(p2);
                    acc.x = fmaf(e2, a2.x, acc.x); acc.y = fmaf(e2, a2.y, acc.y);
                    acc.z = fmaf(e2, a2.z, acc.z); acc.w = fmaf(e2, a2.w, acc.w);
                    denom += e2;
                }
                if (k0 + 3 < n) {
                    float e3 = __expf(p3);
                    acc.x = fmaf(e3, a3.x, acc.x); acc.y = fmaf(e3, a3.y, acc.y);
                    acc.z = fmaf(e3, a3.z, acc.z); acc.w = fmaf(e3, a3.w, acc.w);
                    denom += e3;
                }
            }
        }
        float inv = (end > beg) ? 1.f / denom : 0.f;     // deg==0 -> zero row
        int row = half * 8 + m;
        *(float4*)(stage + row * S_STRIDE + hl * 4) =    // one STS.128
            make_float4(acc.x * inv, acc.y * inv, acc.z * inv, acc.w * inv);
    }
    __syncwarp();

    // ---- FC via mma.sync m16n8k8 tf32 (unchanged from R14 WIN) ----
    int g = lane >> 2, t = lane & 3;
    unsigned A0[8], A1[8], A2[8], A3[8];
    #pragma unroll
    for (int ks = 0; ks < 8; ks++) {
        A0[ks] = to_tf32(stage[ g      * S_STRIDE + ks * 8 + t    ]);
        A1[ks] = to_tf32(stage[(g + 8) * S_STRIDE + ks * 8 + t    ]);
        A2[ks] = to_tf32(stage[ g      * S_STRIDE + ks * 8 + t + 4]);
        A3[ks] = to_tf32(stage[(g + 8) * S_STRIDE + ks * 8 + t + 4]);
    }
    int n0 = nbase + g, n1 = n0 + 8;
    float2* out2 = (float2*)out;

    #pragma unroll 4
    for (int nt = 0; nt < 16; nt++) {
        float2 bb = __ldg((const float2*)b + nt * 4 + t);
        float c0 = bb.x, c1 = bb.y, c2 = bb.x, c3 = bb.y;
        #pragma unroll
        for (int ks = 0; ks < 8; ks++) {
            unsigned b0 = __float_as_uint(Wt_s[(ks * 8 + t    ) * W_STRIDE + nt * 8 + g]);
            unsigned b1 = __float_as_uint(Wt_s[(ks * 8 + t + 4) * W_STRIDE + nt * 8 + g]);
            asm volatile(
                "mma.sync.aligned.m16n8k8.row.col.f32.tf32.tf32.f32 "
                "{%0,%1,%2,%3}, {%4,%5,%6,%7}, {%8,%9}, {%0,%1,%2,%3};"
                : "+f"(c0), "+f"(c1), "+f"(c2), "+f"(c3)
                : "r"(A0[ks]), "r"(A1[ks]), "r"(A2[ks]), "r"(A3[ks]),
                  "r"(b0), "r"(b1));
        }
        c0 = fmaxf(c0, 0.f); c1 = fmaxf(c1, 0.f);
        c2 = fmaxf(c2, 0.f); c3 = fmaxf(c3, 0.f);
        if (n0 < N_NODES) out2[(size_t)n0 * 64 + nt * 4 + t] = make_float2(c0, c1);
        if (n1 < N_NODES) out2[(size_t)n1 * 64 + nt * 4 + t] = make_float2(c2, c3);
    }
}

// ---------------------------------------------------------------------------
// Inputs: hk[f32 N*64], hu[f32 N*64], W[f32 128*64], b[f32 128],
//         src[i32 E], dst[i32 E].  Output: f32 N*128.
// ---------------------------------------------------------------------------
extern "C" void kernel_launch(void* const* d_in, const int* in_sizes, int n_in,
                              void* d_out, int out_size) {
    const float* hk  = (const float*)d_in[0];
    const float* hu  = (const float*)d_in[1];
    const float* W   = (const float*)d_in[2];
    const float* b   = (const float*)d_in[3];
    const int*   src = (const int*)d_in[4];
    const int*   dst = (const int*)d_in[5];
    float* out = (float*)d_out;

    cudaFuncSetAttribute(attn_fc_kernel,
                         cudaFuncAttributeMaxDynamicSharedMemorySize, SMEM_BYTES);

    const int qblocks = (N_EDGES / 4 + 255) / 256;       // 4 edges per thread
    init_kernel<<<(N_NODES + 255) / 256, 256>>>(W);
    count_kernel<<<qblocks, 256>>>(dst);
    scan_fused_kernel<<<SCAN_BLOCKS, 256>>>();
    bin_kernel<<<qblocks, 256>>>(src, dst);
    attn_fc_kernel<<<(N_NODES + 127) / 128, 256, SMEM_BYTES>>>(hk, hu, b, out);
}

// round 16
// speedup vs baseline: 1.5146x; 1.0184x over previous
#include <cuda_runtime.h>

#define N_NODES 100000
#define N_EDGES 1200000
#define D_FEAT  64
#define D_OUT   128
#define SCAN_CHUNK  1024
#define SCAN_BLOCKS ((N_NODES + SCAN_CHUNK - 1) / SCAN_CHUNK)   // 98
#define W_STRIDE 136
#define S_STRIDE 68
#define SMEM_FLOATS (64 * W_STRIDE + 8 * 16 * S_STRIDE)
#define SMEM_BYTES (SMEM_FLOATS * 4)                       // 69632

// Scratch (no allocs allowed)
__device__ int g_esrc[N_EDGES];
__device__ int g_rank[N_EDGES];
__device__ int g_count[N_NODES];
__device__ int g_off[N_NODES + 1];
__device__ int g_bsum[SCAN_BLOCKS];
__device__ int g_bscan[SCAN_BLOCKS];
__device__ int g_arrive;
__device__ int g_release;
__device__ float g_Wt[64 * W_STRIDE];

// ---------------------------------------------------------------------------
// K0: zero counters, reset scan flags, build tf32 Wt.
// ---------------------------------------------------------------------------
__global__ void __launch_bounds__(256) init_kernel(const float* __restrict__ W) {
    int i = blockIdx.x * 256 + threadIdx.x;
    if (i < N_NODES) g_count[i] = 0;
    if (i == 0) { g_arrive = 0; g_release = 0; }
    if (i < 64 * W_STRIDE) {
        int k = i / W_STRIDE, n = i % W_STRIDE;
        float v = (n < D_OUT) ? __ldg(&W[n * D_FEAT + k]) : 0.f;
        unsigned t;
        asm("cvt.rna.tf32.f32 %0, %1;" : "=r"(t) : "f"(v));
        g_Wt[i] = __uint_as_float(t);
    }
}

// ---------------------------------------------------------------------------
// K1: count+rank, 4 edges/thread.
// ---------------------------------------------------------------------------
__global__ void __launch_bounds__(256) count_kernel(const int* __restrict__ dst) {
    int q = blockIdx.x * 256 + threadIdx.x;
    if (q * 4 >= N_EDGES) return;
    int4 d4 = __ldg((const int4*)dst + q);
    int4 r4;
    r4.x = ((unsigned)d4.x < N_NODES) ? atomicAdd(&g_count[d4.x], 1) : 0;
    r4.y = ((unsigned)d4.y < N_NODES) ? atomicAdd(&g_count[d4.y], 1) : 0;
    r4.z = ((unsigned)d4.z < N_NODES) ? atomicAdd(&g_count[d4.z], 1) : 0;
    r4.w = ((unsigned)d4.w < N_NODES) ? atomicAdd(&g_count[d4.w], 1) : 0;
    ((int4*)g_rank)[q] = r4;
}

// ---------------------------------------------------------------------------
// K2: single-kernel two-level exclusive scan.
// ---------------------------------------------------------------------------
__global__ void __launch_bounds__(256) scan_fused_kernel() {
    __shared__ int sh[256];
    __shared__ int sp[128];
    __shared__ int s_last;
    int b = blockIdx.x, tid = threadIdx.x;
    int base = b * SCAN_CHUNK + tid * 4;

    int c[4]; int s = 0;
    #pragma unroll
    for (int j = 0; j < 4; j++) {
        int i = base + j;
        c[j] = (i < N_NODES) ? g_count[i] : 0;
        s += c[j];
    }
    sh[tid] = s; __syncthreads();
    for (int o = 128; o; o >>= 1) { if (tid < o) sh[tid] += sh[tid + o]; __syncthreads(); }
    if (tid == 0) {
        g_bsum[b] = sh[0];
        __threadfence();
        s_last = (atomicAdd(&g_arrive, 1) == SCAN_BLOCKS - 1);
    }
    __syncthreads();

    if (s_last) {
        int v = (tid < SCAN_BLOCKS) ? g_bsum[tid] : 0;
        if (tid < 128) sp[tid] = v;
        __syncthreads();
        #pragma unroll
        for (int o = 1; o < 128; o <<= 1) {
            int t = (tid < 128 && tid >= o) ? sp[tid - o] : 0;
            __syncthreads();
            if (tid < 128) sp[tid] += t;
            __syncthreads();
        }
        if (tid < SCAN_BLOCKS) g_bscan[tid] = sp[tid] - v;
        if (tid == 127) g_off[N_NODES] = sp[127];
        __threadfence();
        __syncthreads();
        if (tid == 0) atomicExch(&g_release, 1);
    }

    if (tid == 0) while (atomicAdd(&g_release, 0) == 0) {}
    __syncthreads();

    sh[tid] = s; __syncthreads();
    int v2 = s;
    #pragma unroll
    for (int o = 1; o < 256; o <<= 1) {
        int t = (tid >= o) ? sh[tid - o] : 0;
        __syncthreads();
        sh[tid] += t;
        __syncthreads();
    }
    int run = g_bscan[b] + (sh[tid] - v2);
    #pragma unroll
    for (int j = 0; j < 4; j++) {
        int i = base + j;
        if (i < N_NODES) { g_off[i] = run; run += c[j]; }
    }
}

// ---------------------------------------------------------------------------
// K3: bin, 4 edges/thread — atomic-free.
// ---------------------------------------------------------------------------
__global__ void __launch_bounds__(256) bin_kernel(
    const int* __restrict__ src, const int* __restrict__ dst)
{
    int q = blockIdx.x * 256 + threadIdx.x;
    if (q * 4 >= N_EDGES) return;
    int4 d4 = __ldg((const int4*)dst + q);
    int4 r4 = __ldg((const int4*)g_rank + q);
    int4 s4 = __ldg((const int4*)src + q);
    if ((unsigned)d4.x < N_NODES) g_esrc[__ldg(&g_off[d4.x]) + r4.x] = s4.x;
    if ((unsigned)d4.y < N_NODES) g_esrc[__ldg(&g_off[d4.y]) + r4.y] = s4.y;
    if ((unsigned)d4.z < N_NODES) g_esrc[__ldg(&g_off[d4.z]) + r4.z] = s4.z;
    if ((unsigned)d4.w < N_NODES) g_esrc[__ldg(&g_off[d4.w]) + r4.w] = s4.w;
}

// ---------------------------------------------------------------------------
// K4: attention + tensor-core FC, now SOFTWARE-PIPELINED ACROSS NODES:
//  - all 8 node bounds fetched in ONE coalesced LDG (then 2 shfl per node)
//  - next node's hu row and first esrc block prefetched during current node
// This removes the ~750-cycle dependent front chain (off -> hu -> esrc) that
// every node iteration previously exposed — the one latency never attacked
// by R9/R15's intra-block pipelining.
// ---------------------------------------------------------------------------
__device__ __forceinline__ float dot4(const float4 a, const float4 u) {
    return fmaf(a.x, u.x, fmaf(a.y, u.y, fmaf(a.z, u.z, a.w * u.w)));
}

__device__ __forceinline__ unsigned to_tf32(float x) {
    unsigned t;
    asm("cvt.rna.tf32.f32 %0, %1;" : "=r"(t) : "f"(x));
    return t;
}

// process one <=16-edge block (R15 quad body, unchanged)
__device__ __forceinline__ void process16(
    unsigned hm, int hl, const float4* __restrict__ hk4,
    const float4 u, int srcid, int n, float4& acc, float& denom)
{
    for (int k0 = 0; k0 < n; k0 += 4) {
        int s0 = __shfl_sync(hm, srcid, min(k0 + 0, 15), 16);
        int s1 = __shfl_sync(hm, srcid, min(k0 + 1, 15), 16);
        int s2 = __shfl_sync(hm, srcid, min(k0 + 2, 15), 16);
        int s3 = __shfl_sync(hm, srcid, min(k0 + 3, 15), 16);
        float4 a0 = make_float4(0.f, 0.f, 0.f, 0.f);
        float4 a1 = a0, a2 = a0, a3 = a0;
        a0 = __ldg(hk4 + (size_t)s0 * 16 + hl);
        if (k0 + 1 < n) a1 = __ldg(hk4 + (size_t)s1 * 16 + hl);
        if (k0 + 2 < n) a2 = __ldg(hk4 + (size_t)s2 * 16 + hl);
        if (k0 + 3 < n) a3 = __ldg(hk4 + (size_t)s3 * 16 + hl);

        float p0 = dot4(a0, u), p1 = dot4(a1, u);
        float p2 = dot4(a2, u), p3 = dot4(a3, u);
        #pragma unroll
        for (int o = 8; o; o >>= 1) {
            p0 += __shfl_xor_sync(hm, p0, o, 16);
            p1 += __shfl_xor_sync(hm, p1, o, 16);
            p2 += __shfl_xor_sync(hm, p2, o, 16);
            p3 += __shfl_xor_sync(hm, p3, o, 16);
        }
        {
            float e0 = __expf(p0);
            acc.x = fmaf(e0, a0.x, acc.x); acc.y = fmaf(e0, a0.y, acc.y);
            acc.z = fmaf(e0, a0.z, acc.z); acc.w = fmaf(e0, a0.w, acc.w);
            denom += e0;
        }
        if (k0 + 1 < n) {
            float e1 = __expf(p1);
            acc.x = fmaf(e1, a1.x, acc.x); acc.y = fmaf(e1, a1.y, acc.y);
            acc.z = fmaf(e1, a1.z, acc.z); acc.w = fmaf(e1, a1.w, acc.w);
            denom += e1;
        }
        if (k0 + 2 < n) {
            float e2 = __expf(p2);
            acc.x = fmaf(e2, a2.x, acc.x); acc.y = fmaf(e2, a2.y, acc.y);
            acc.z = fmaf(e2, a2.z, acc.z); acc.w = fmaf(e2, a2.w, acc.w);
            denom += e2;
        }
        if (k0 + 3 < n) {
            float e3 = __expf(p3);
            acc.x = fmaf(e3, a3.x, acc.x); acc.y = fmaf(e3, a3.y, acc.y);
            acc.z = fmaf(e3, a3.z, acc.z); acc.w = fmaf(e3, a3.w, acc.w);
            denom += e3;
        }
    }
}

extern __shared__ float sh[];   // [0,8704): Wt_s  [8704,17408): staging

__global__ void __launch_bounds__(256) attn_fc_kernel(
    const float* __restrict__ hk, const float* __restrict__ hu,
    const float* __restrict__ b, float* __restrict__ out)
{
    float* Wt_s = sh;
    int tid = threadIdx.x;
    for (int i = tid; i < 64 * W_STRIDE; i += 256)
        Wt_s[i] = g_Wt[i];
    __syncthreads();

    int wid = tid >> 5, lane = tid & 31;
    int half = lane >> 4, hl = lane & 15;
    unsigned hm = half ? 0xFFFF0000u : 0x0000FFFFu;
    float* stage = sh + 64 * W_STRIDE + wid * 16 * S_STRIDE;
    const float4* hk4 = (const float4*)hk;
    const float4* hu4 = (const float4*)hu;

    int nbase = (blockIdx.x * 8 + wid) * 16;
    int hbase = nbase + half * 8;

    // ---- cross-node pipeline setup: all bounds in ONE coalesced load ----
    int offv = __ldg(&g_off[min(hbase + hl, N_NODES)]);  // lanes 0..8 used
    float4 u_cur = __ldg(hu4 + (size_t)min(hbase, N_NODES - 1) * 16 + hl);
    int srcid_cur;
    {
        int beg0 = __shfl_sync(hm, offv, 0, 16);
        int end0 = __shfl_sync(hm, offv, 1, 16);
        int n0 = min(16, end0 - beg0);
        srcid_cur = (hl < n0) ? __ldg(&g_esrc[beg0 + hl]) : 0;
    }

    for (int m = 0; m < 8; m++) {
        int node = hbase + m;
        if (node >= N_NODES) break;                      // half-uniform
        float4 u = u_cur;
        int srcid0 = srcid_cur;
        int beg = __shfl_sync(hm, offv, m, 16);
        int end = __shfl_sync(hm, offv, m + 1, 16);

        // ---- prefetch node m+1's front (hu row + first esrc block) ----
        if (m < 7) {                                     // uniform predicate
            u_cur = __ldg(hu4 + (size_t)min(node + 1, N_NODES - 1) * 16 + hl);
            int beg_n = end;
            int end_n = __shfl_sync(hm, offv, m + 2, 16);
            int nn = min(16, end_n - beg_n);
            if (hl < nn) srcid_cur = __ldg(&g_esrc[beg_n + hl]);
        }

        // ---- process this node's edges (first block prefetched) ----
        float4 acc = make_float4(0.f, 0.f, 0.f, 0.f);
        float denom = 0.f;
        process16(hm, hl, hk4, u, srcid0, min(16, end - beg), acc, denom);
        for (int base = beg + 16; base < end; base += 16) {   // deg>16: rare
            int n = min(16, end - base);
            int srcid = (hl < n) ? __ldg(&g_esrc[base + hl]) : 0;
            process16(hm, hl, hk4, u, srcid, n, acc, denom);
        }

        float inv = (end > beg) ? 1.f / denom : 0.f;     // deg==0 -> zero row
        int row = half * 8 + m;
        *(float4*)(stage + row * S_STRIDE + hl * 4) =
            make_float4(acc.x * inv, acc.y * inv, acc.z * inv, acc.w * inv);
    }
    __syncwarp();

    // ---- FC via mma.sync m16n8k8 tf32 (unchanged from R14 WIN) ----
    int g = lane >> 2, t = lane & 3;
    unsigned A0[8], A1[8], A2[8], A3[8];
    #pragma unroll
    for (int ks = 0; ks < 8; ks++) {
        A0[ks] = to_tf32(stage[ g      * S_STRIDE + ks * 8 + t    ]);
        A1[ks] = to_tf32(stage[(g + 8) * S_STRIDE + ks * 8 + t    ]);
        A2[ks] = to_tf32(stage[ g      * S_STRIDE + ks * 8 + t + 4]);
        A3[ks] = to_tf32(stage[(g + 8) * S_STRIDE + ks * 8 + t + 4]);
    }
    int n0 = nbase + g, n1 = n0 + 8;
    float2* out2 = (float2*)out;

    #pragma unroll 4
    for (int nt = 0; nt < 16; nt++) {
        float2 bb = __ldg((const float2*)b + nt * 4 + t);
        float c0 = bb.x, c1 = bb.y, c2 = bb.x, c3 = bb.y;
        #pragma unroll
        for (int ks = 0; ks < 8; ks++) {
            unsigned b0 = __float_as_uint(Wt_s[(ks * 8 + t    ) * W_STRIDE + nt * 8 + g]);
            unsigned b1 = __float_as_uint(Wt_s[(ks * 8 + t + 4) * W_STRIDE + nt * 8 + g]);
            asm volatile(
                "mma.sync.aligned.m16n8k8.row.col.f32.tf32.tf32.f32 "
                "{%0,%1,%2,%3}, {%4,%5,%6,%7}, {%8,%9}, {%0,%1,%2,%3};"
                : "+f"(c0), "+f"(c1), "+f"(c2), "+f"(c3)
                : "r"(A0[ks]), "r"(A1[ks]), "r"(A2[ks]), "r"(A3[ks]),
                  "r"(b0), "r"(b1));
        }
        c0 = fmaxf(c0, 0.f); c1 = fmaxf(c1, 0.f);
        c2 = fmaxf(c2, 0.f); c3 = fmaxf(c3, 0.f);
        if (n0 < N_NODES) out2[(size_t)n0 * 64 + nt * 4 + t] = make_float2(c0, c1);
        if (n1 < N_NODES) out2[(size_t)n1 * 64 + nt * 4 + t] = make_float2(c2, c3);
    }
}

// ---------------------------------------------------------------------------
// Inputs: hk[f32 N*64], hu[f32 N*64], W[f32 128*64], b[f32 128],
//         src[i32 E], dst[i32 E].  Output: f32 N*128.
// ---------------------------------------------------------------------------
extern "C" void kernel_launch(void* const* d_in, const int* in_sizes, int n_in,
                              void* d_out, int out_size) {
    const float* hk  = (const float*)d_in[0];
    const float* hu  = (const float*)d_in[1];
    const float* W   = (const float*)d_in[2];
    const float* b   = (const float*)d_in[3];
    const int*   src = (const int*)d_in[4];
    const int*   dst = (const int*)d_in[5];
    float* out = (float*)d_out;

    cudaFuncSetAttribute(attn_fc_kernel,
                         cudaFuncAttributeMaxDynamicSharedMemorySize, SMEM_BYTES);

    const int qblocks = (N_EDGES / 4 + 255) / 256;
    init_kernel<<<(N_NODES + 255) / 256, 256>>>(W);
    count_kernel<<<qblocks, 256>>>(dst);
    scan_fused_kernel<<<SCAN_BLOCKS, 256>>>();
    bin_kernel<<<qblocks, 256>>>(src, dst);
    attn_fc_kernel<<<(N_NODES + 127) / 128, 256, SMEM_BYTES>>>(hk, hu, b, out);
}